// round 1
// baseline (speedup 1.0000x reference)
#include <cuda_runtime.h>
#include <math.h>

#define L 1024
#define D 512
#define H 256

// Scratch (allocation-free): projections stored h-major, raw scores.
__device__ float g_p[2][H][L];   // [0] = pa^T, [1] = (pb + b1)^T
__device__ float g_s[L][L];      // raw (un-symmetrized) scores

// ---------------------------------------------------------------------------
// Kernel 1: P[sel][h][l] = sum_d W1[h][sel*D + d] * X[l][d]   (+ b1[h] if sel)
// 64x64 tile, BK=16, 256 threads, 4x4 register micro-tile.
// ---------------------------------------------------------------------------
__global__ __launch_bounds__(256) void gemm_proj_kernel(
    const float* __restrict__ X,
    const float* __restrict__ W1,
    const float* __restrict__ b1)
{
    const int sel = blockIdx.z;
    const int h0  = blockIdx.y * 64;
    const int l0  = blockIdx.x * 64;

    __shared__ float As[16][68];   // [k][h], padded (272B row stride, 16B aligned)
    __shared__ float Bs[16][68];   // [k][l]

    const int tid = threadIdx.x;
    const int ty  = tid >> 4;          // 0..15
    const int tx  = tid & 15;          // 0..15
    const int lr  = tid >> 2;          // 0..63  loader row
    const int lk  = (tid & 3) * 4;     // 0,4,8,12 loader k offset

    float acc[4][4] = {};

    for (int k0 = 0; k0 < D; k0 += 16) {
        // A: W1 rows h0+lr, cols sel*D + k0 + lk .. +3 (transpose into smem)
        float4 av = *(const float4*)(W1 + (size_t)(h0 + lr) * (2 * D) + sel * D + k0 + lk);
        As[lk + 0][lr] = av.x; As[lk + 1][lr] = av.y;
        As[lk + 2][lr] = av.z; As[lk + 3][lr] = av.w;
        // B: X rows l0+lr, cols k0+lk .. +3
        float4 bv = *(const float4*)(X + (size_t)(l0 + lr) * D + k0 + lk);
        Bs[lk + 0][lr] = bv.x; Bs[lk + 1][lr] = bv.y;
        Bs[lk + 2][lr] = bv.z; Bs[lk + 3][lr] = bv.w;
        __syncthreads();

        #pragma unroll
        for (int kk = 0; kk < 16; kk++) {
            float4 a4 = *(const float4*)&As[kk][ty * 4];
            float4 b4 = *(const float4*)&Bs[kk][tx * 4];
            float a[4] = {a4.x, a4.y, a4.z, a4.w};
            float b[4] = {b4.x, b4.y, b4.z, b4.w};
            #pragma unroll
            for (int r = 0; r < 4; r++)
                #pragma unroll
                for (int c = 0; c < 4; c++)
                    acc[r][c] = fmaf(a[r], b[c], acc[r][c]);
        }
        __syncthreads();
    }

    #pragma unroll
    for (int r = 0; r < 4; r++) {
        const int h = h0 + ty * 4 + r;
        const float bias = (sel == 1) ? b1[h] : 0.0f;
        float4 o;
        o.x = acc[r][0] + bias; o.y = acc[r][1] + bias;
        o.z = acc[r][2] + bias; o.w = acc[r][3] + bias;
        *(float4*)&g_p[sel][h][l0 + tx * 4] = o;
    }
}

// ---------------------------------------------------------------------------
// Kernel 2: s[i][j] = sum_h relu(pa[i,h] + pbb[j,h]) * w2[h]
// 64x64 output tile per block, H chunked by 16, 4x4 register micro-tile.
// ---------------------------------------------------------------------------
__global__ __launch_bounds__(256) void pairwise_kernel(const float* __restrict__ W2)
{
    const int J = blockIdx.x * 64;   // j (cols)
    const int I = blockIdx.y * 64;   // i (rows)

    __shared__ float Pa[16][68];     // [h_local][i_local]
    __shared__ float Pb[16][68];     // [h_local][j_local]
    __shared__ float w2s[H];

    const int tid  = threadIdx.x;
    const int ty   = tid >> 4;
    const int tx   = tid & 15;
    const int lrow = tid >> 4;          // 0..15 (h within chunk)
    const int lcol = (tid & 15) * 4;    // 0..60 (i/j offset)

    if (tid < H) w2s[tid] = W2[tid];    // H == 256 == blockDim

    float acc[4][4] = {};

    for (int hb = 0; hb < H; hb += 16) {
        float4 av = *(const float4*)&g_p[0][hb + lrow][I + lcol];
        *(float4*)&Pa[lrow][lcol] = av;
        float4 bv = *(const float4*)&g_p[1][hb + lrow][J + lcol];
        *(float4*)&Pb[lrow][lcol] = bv;
        __syncthreads();

        #pragma unroll
        for (int kk = 0; kk < 16; kk++) {
            float4 a4 = *(const float4*)&Pa[kk][ty * 4];
            float4 b4 = *(const float4*)&Pb[kk][tx * 4];
            const float w = w2s[hb + kk];
            float a[4] = {a4.x, a4.y, a4.z, a4.w};
            float b[4] = {b4.x, b4.y, b4.z, b4.w};
            #pragma unroll
            for (int r = 0; r < 4; r++)
                #pragma unroll
                for (int c = 0; c < 4; c++)
                    acc[r][c] = fmaf(fmaxf(a[r] + b[c], 0.0f), w, acc[r][c]);
        }
        __syncthreads();
    }

    #pragma unroll
    for (int r = 0; r < 4; r++) {
        float4 o;
        o.x = acc[r][0]; o.y = acc[r][1]; o.z = acc[r][2]; o.w = acc[r][3];
        *(float4*)&g_s[I + ty * 4 + r][J + tx * 4] = o;
    }
}

// ---------------------------------------------------------------------------
// Kernel 3: out[i][j] = sigmoid(0.5*(s[i][j] + s[j][i]) + b2)
// Tiled transpose via smem so both global reads stay coalesced.
// ---------------------------------------------------------------------------
__global__ __launch_bounds__(256) void sym_sigmoid_kernel(
    float* __restrict__ out, const float* __restrict__ b2p)
{
    __shared__ float ts[32][33];
    const int bi = blockIdx.y, bj = blockIdx.x;
    const int tx = threadIdx.x;        // 0..31
    const int ty = threadIdx.y;        // 0..7
    const float b2 = b2p[0];

    // ts[a][b] = s[bj*32 + a][bi*32 + b]  (the transpose-source tile)
    #pragma unroll
    for (int rr = ty; rr < 32; rr += 8)
        ts[rr][tx] = g_s[bj * 32 + rr][bi * 32 + tx];
    __syncthreads();

    #pragma unroll
    for (int rr = ty; rr < 32; rr += 8) {
        const int i = bi * 32 + rr;
        const int j = bj * 32 + tx;
        const float v = 0.5f * (g_s[i][j] + ts[tx][rr]) + b2;
        out[(size_t)i * L + j] = 1.0f / (1.0f + expf(-v));
    }
}

// ---------------------------------------------------------------------------
extern "C" void kernel_launch(void* const* d_in, const int* in_sizes, int n_in,
                              void* d_out, int out_size)
{
    const float* X  = (const float*)d_in[0];  // [L, D]
    const float* W1 = (const float*)d_in[1];  // [H, 2D]
    const float* b1 = (const float*)d_in[2];  // [H]
    const float* W2 = (const float*)d_in[3];  // [1, H]
    const float* b2 = (const float*)d_in[4];  // [1]

    gemm_proj_kernel<<<dim3(L / 64, H / 64, 2), 256>>>(X, W1, b1);
    pairwise_kernel<<<dim3(L / 64, L / 64), 256>>>(W2);
    sym_sigmoid_kernel<<<dim3(L / 32, L / 32), dim3(32, 8)>>>((float*)d_out, b2);
}

// round 2
// speedup vs baseline: 1.0052x; 1.0052x over previous
#include <cuda_runtime.h>
#include <math.h>

#define L 1024
#define D 512
#define H 256

typedef unsigned long long ull;

// Scratch (allocation-free)
__device__ float g_p[2][H][L];   // [0]=pa^T, [1]=(pb+b1)^T  (h-major)
__device__ float g_s[L][L];      // A[i][j] = sum_h (w_h/2)|pa_i + pbb_j|
__device__ float g_t[L];         // t_i = 0.5*(u_i + v_i) rank-1 term

// ---- packed f32x2 helpers (Blackwell) --------------------------------------
__device__ __forceinline__ ull pack2(float x) {
    ull r;
    asm("mov.b64 %0, {%1, %1};" : "=l"(r) : "r"(__float_as_uint(x)));
    return r;
}
__device__ __forceinline__ ull add2(ull a, ull b) {
    ull r; asm("add.rn.f32x2 %0, %1, %2;" : "=l"(r) : "l"(a), "l"(b)); return r;
}
__device__ __forceinline__ ull fma2(ull a, ull b, ull c) {
    ull r; asm("fma.rn.f32x2 %0, %1, %2, %3;" : "=l"(r) : "l"(a), "l"(b), "l"(c)); return r;
}
__device__ __forceinline__ ull abs2(ull a) { return a & 0x7FFFFFFF7FFFFFFFULL; }

// ---------------------------------------------------------------------------
// Kernel 1: P[sel][h][l] = sum_d W1[h][sel*D+d] * X[l][d]  (+ b1[h] if sel)
// 64x64 tile, BK=16, 256 thr, 4x4 micro-tile, packed FFMA2, reg double-buffer.
// ---------------------------------------------------------------------------
__global__ __launch_bounds__(256) void gemm_proj_kernel(
    const float* __restrict__ X,
    const float* __restrict__ W1,
    const float* __restrict__ b1)
{
    const int sel = blockIdx.z;
    const int h0  = blockIdx.y * 64;
    const int l0  = blockIdx.x * 64;

    __shared__ float As[16][68];   // [k][h]
    __shared__ float Bs[16][68];   // [k][l]

    const int tid = threadIdx.x;
    const int ty  = tid >> 4;
    const int tx  = tid & 15;
    const int lr  = tid >> 2;
    const int lk  = (tid & 3) * 4;

    ull acc[4][2] = {};

    const float* aptr = W1 + (size_t)(h0 + lr) * (2 * D) + sel * D + lk;
    const float* bptr = X  + (size_t)(l0 + lr) * D + lk;

    float4 av = *(const float4*)(aptr);
    float4 bv = *(const float4*)(bptr);

    for (int k0 = 0; k0 < D; k0 += 16) {
        As[lk + 0][lr] = av.x; As[lk + 1][lr] = av.y;
        As[lk + 2][lr] = av.z; As[lk + 3][lr] = av.w;
        Bs[lk + 0][lr] = bv.x; Bs[lk + 1][lr] = bv.y;
        Bs[lk + 2][lr] = bv.z; Bs[lk + 3][lr] = bv.w;
        __syncthreads();

        if (k0 + 16 < D) {               // prefetch next chunk (hides L2 lat)
            av = *(const float4*)(aptr + k0 + 16);
            bv = *(const float4*)(bptr + k0 + 16);
        }

        #pragma unroll
        for (int kk = 0; kk < 16; kk++) {
            float4     a4 = *(const float4*)&As[kk][ty * 4];
            ulonglong2 bp = *(const ulonglong2*)&Bs[kk][tx * 4];
            float a[4] = {a4.x, a4.y, a4.z, a4.w};
            #pragma unroll
            for (int r = 0; r < 4; r++) {
                ull ap = pack2(a[r]);
                acc[r][0] = fma2(ap, bp.x, acc[r][0]);
                acc[r][1] = fma2(ap, bp.y, acc[r][1]);
            }
        }
        __syncthreads();
    }

    #pragma unroll
    for (int r = 0; r < 4; r++) {
        const int h = h0 + ty * 4 + r;
        const float bias = (sel == 1) ? b1[h] : 0.0f;
        ull b2p = pack2(bias);
        ulonglong2 o;
        o.x = add2(acc[r][0], b2p);
        o.y = add2(acc[r][1], b2p);
        *(ulonglong2*)&g_p[sel][h][l0 + tx * 4] = o;
    }
}

// ---------------------------------------------------------------------------
// Kernel 2: g_t[i] = sum_h (w_h/4) * (pa[i,h] + pbb[i,h])
// ---------------------------------------------------------------------------
__global__ __launch_bounds__(64) void uv_kernel(const float* __restrict__ W2)
{
    const int i = blockIdx.x * 64 + threadIdx.x;
    float a0 = 0.f, a1 = 0.f, a2 = 0.f, a3 = 0.f;
    #pragma unroll 4
    for (int h = 0; h < H; h += 4) {
        a0 = fmaf(g_p[0][h + 0][i] + g_p[1][h + 0][i], W2[h + 0], a0);
        a1 = fmaf(g_p[0][h + 1][i] + g_p[1][h + 1][i], W2[h + 1], a1);
        a2 = fmaf(g_p[0][h + 2][i] + g_p[1][h + 2][i], W2[h + 2], a2);
        a3 = fmaf(g_p[0][h + 3][i] + g_p[1][h + 3][i], W2[h + 3], a3);
    }
    g_t[i] = 0.25f * ((a0 + a1) + (a2 + a3));
}

// ---------------------------------------------------------------------------
// Kernel 3: A[i][j] = sum_h (w_h/2) * |pa[i,h] + pbb[j,h]|
// 64x64 tile, packed f32x2: add2 + and.b64 + fma2 per element-pair.
// ---------------------------------------------------------------------------
__global__ __launch_bounds__(256) void pairwise_kernel(const float* __restrict__ W2)
{
    const int J = blockIdx.x * 64;
    const int I = blockIdx.y * 64;

    __shared__ float Pa[16][68];
    __shared__ float Pb[16][68];
    __shared__ float w2s[H];       // pre-halved

    const int tid  = threadIdx.x;
    const int ty   = tid >> 4;
    const int tx   = tid & 15;
    const int lrow = tid >> 4;
    const int lcol = (tid & 15) * 4;

    w2s[tid] = 0.5f * W2[tid];     // H == 256 == blockDim

    ull acc[4][2] = {};

    float4 av = *(const float4*)&g_p[0][lrow][I + lcol];
    float4 bv = *(const float4*)&g_p[1][lrow][J + lcol];

    for (int hb = 0; hb < H; hb += 16) {
        *(float4*)&Pa[lrow][lcol] = av;
        *(float4*)&Pb[lrow][lcol] = bv;
        __syncthreads();

        if (hb + 16 < H) {
            av = *(const float4*)&g_p[0][hb + 16 + lrow][I + lcol];
            bv = *(const float4*)&g_p[1][hb + 16 + lrow][J + lcol];
        }

        #pragma unroll
        for (int kk = 0; kk < 16; kk++) {
            float4     a4 = *(const float4*)&Pa[kk][ty * 4];
            ulonglong2 bp = *(const ulonglong2*)&Pb[kk][tx * 4];
            ull wp = pack2(w2s[hb + kk]);
            float a[4] = {a4.x, a4.y, a4.z, a4.w};
            #pragma unroll
            for (int r = 0; r < 4; r++) {
                ull ap = pack2(a[r]);
                ull x0 = add2(ap, bp.x);
                ull x1 = add2(ap, bp.y);
                acc[r][0] = fma2(abs2(x0), wp, acc[r][0]);
                acc[r][1] = fma2(abs2(x1), wp, acc[r][1]);
            }
        }
        __syncthreads();
    }

    #pragma unroll
    for (int r = 0; r < 4; r++) {
        ulonglong2 o; o.x = acc[r][0]; o.y = acc[r][1];
        *(ulonglong2*)&g_s[I + ty * 4 + r][J + tx * 4] = o;
    }
}

// ---------------------------------------------------------------------------
// Kernel 4: out[i][j] = sigmoid(0.5*(A[i][j]+A[j][i]) + t_i + t_j + b2)
// ---------------------------------------------------------------------------
__global__ __launch_bounds__(256) void sym_sigmoid_kernel(
    float* __restrict__ out, const float* __restrict__ b2p)
{
    __shared__ float ts[32][33];
    const int bi = blockIdx.y, bj = blockIdx.x;
    const int tx = threadIdx.x;
    const int ty = threadIdx.y;
    const float b2 = b2p[0];

    #pragma unroll
    for (int rr = ty; rr < 32; rr += 8)
        ts[rr][tx] = g_s[bj * 32 + rr][bi * 32 + tx];
    __syncthreads();

    const int j  = bj * 32 + tx;
    const float tj = g_t[j];
    #pragma unroll
    for (int rr = ty; rr < 32; rr += 8) {
        const int i = bi * 32 + rr;
        const float v = 0.5f * (g_s[i][j] + ts[tx][rr]) + g_t[i] + tj + b2;
        out[(size_t)i * L + j] = 1.0f / (1.0f + __expf(-v));
    }
}

// ---------------------------------------------------------------------------
extern "C" void kernel_launch(void* const* d_in, const int* in_sizes, int n_in,
                              void* d_out, int out_size)
{
    const float* X  = (const float*)d_in[0];  // [L, D]
    const float* W1 = (const float*)d_in[1];  // [H, 2D]
    const float* b1 = (const float*)d_in[2];  // [H]
    const float* W2 = (const float*)d_in[3];  // [1, H]
    const float* b2 = (const float*)d_in[4];  // [1]

    gemm_proj_kernel<<<dim3(L / 64, H / 64, 2), 256>>>(X, W1, b1);
    uv_kernel<<<L / 64, 64>>>(W2);
    pairwise_kernel<<<dim3(L / 64, L / 64), 256>>>(W2);
    sym_sigmoid_kernel<<<dim3(L / 32, L / 32), dim3(32, 8)>>>((float*)d_out, b2);
}